// round 10
// baseline (speedup 1.0000x reference)
#include <cuda_runtime.h>
#include <cuda_bf16.h>
#include <cstdint>

// GraphAttentionLayer: out = elu(softmax(h_j @ a_j + const) @ h_j)
// SINGLE kernel. Bulk-copy (cp.async.bulk -> UBLKCP) double-buffered 32KB
// tiles into smem with mbarrier expect_tx: bandwidth comes from bulk-engine
// depth, NOT warp count (LDG path measured to cap at ~4.2TB/s regardless of
// occupancy). 16 consumer warps read rows from smem, quad dot + shfl reduce,
// rare-rescale online softmax. Last-block finalize combines partials L2-hot.
// h_i . a_i is a constant logit shift -> cancels in softmax -> skipped.

#define D         128
#define NB        296
#define NT        512
#define WPB       (NT / 32)
#define GRP       (NT / D)
#define ROWB      512                   // bytes per row
#define TROWS     64                    // rows per tile
#define TILE_B    (TROWS * ROWB)        // 32KB
#define RING_B    (2 * TILE_B)          // 64KB
#define SMEM_B    (RING_B + 64)         // + mbarriers

__device__ float g_m[NB];
__device__ float g_s[NB];
__device__ float g_acc[NB * D];
__device__ unsigned int g_count;

__device__ __forceinline__ float dot4(const float4& h, const float4& a) {
    return h.x * a.x + h.y * a.y + h.z * a.z + h.w * a.w;
}

__device__ __forceinline__ void upd(float d, const float4& h,
                                    float& m, float& s, float4& acc) {
    if (d > m) {
        float c = __expf(m - d);
        s = s * c + 1.0f;
        acc.x = acc.x * c + h.x;
        acc.y = acc.y * c + h.y;
        acc.z = acc.z * c + h.z;
        acc.w = acc.w * c + h.w;
        m = d;
    } else {
        float w = __expf(d - m);
        s += w;
        acc.x += w * h.x; acc.y += w * h.y;
        acc.z += w * h.z; acc.w += w * h.w;
    }
}

__device__ __forceinline__ void mbar_wait(uint32_t mbar, uint32_t parity) {
    asm volatile(
        "{\n\t.reg .pred P;\n\t"
        "W%=:\n\t"
        "mbarrier.try_wait.parity.acquire.cta.shared::cta.b64 P, [%0], %1, 0x989680;\n\t"
        "@P bra D%=;\n\t"
        "bra W%=;\n\t"
        "D%=:\n\t}"
        :: "r"(mbar), "r"(parity) : "memory");
}

extern __shared__ __align__(16) unsigned char smem[];

__global__ __launch_bounds__(NT)
void gat_fused(const float* __restrict__ hj, const float* __restrict__ a,
               int nrows, float* __restrict__ out) {
    const int tid  = threadIdx.x;
    const int warp = tid >> 5;
    const int lane = tid & 31;

    const uint32_t sbase = (uint32_t)__cvta_generic_to_shared(smem);
    const uint32_t fullb[2]  = { sbase + RING_B,      sbase + RING_B + 8  };
    const uint32_t emptyb[2] = { sbase + RING_B + 16, sbase + RING_B + 24 };

    if (tid == 0) {
        asm volatile("mbarrier.init.shared.b64 [%0], 1;"  :: "r"(fullb[0])  : "memory");
        asm volatile("mbarrier.init.shared.b64 [%0], 1;"  :: "r"(fullb[1])  : "memory");
        asm volatile("mbarrier.init.shared.b64 [%0], %1;" :: "r"(emptyb[0]), "r"(NT) : "memory");
        asm volatile("mbarrier.init.shared.b64 [%0], %1;" :: "r"(emptyb[1]), "r"(NT) : "memory");
        asm volatile("fence.proxy.async.shared::cta;" ::: "memory");
    }
    __syncthreads();

    const float4 aj = *reinterpret_cast<const float4*>(a + D + lane * 4);

    const int chunk = (nrows + NB - 1) / NB;
    const int r0b   = blockIdx.x * chunk;
    int nblk = nrows - r0b;
    if (nblk > chunk) nblk = chunk;
    if (nblk < 0) nblk = 0;
    const int T = (nblk + TROWS - 1) / TROWS;

    const float* src0 = hj + (size_t)r0b * D;

    // Prologue: issue up to 2 tiles
    if (tid == 0) {
        for (int t = 0; t < T && t < 2; ++t) {
            int rows = nblk - t * TROWS; if (rows > TROWS) rows = TROWS;
            uint32_t bytes = (uint32_t)rows * ROWB;
            uint32_t dst = sbase + (t & 1) * TILE_B;
            asm volatile("mbarrier.arrive.expect_tx.shared.b64 _, [%0], %1;"
                         :: "r"(fullb[t & 1]), "r"(bytes) : "memory");
            asm volatile("cp.async.bulk.shared::cluster.global.mbarrier::complete_tx::bytes "
                         "[%0], [%1], %2, [%3];"
                         :: "r"(dst), "l"(src0 + (size_t)t * TROWS * D),
                            "r"(bytes), "r"(fullb[t & 1]) : "memory");
        }
    }

    float  m = -1e30f;
    float  s = 0.0f;
    float4 acc = make_float4(0.f, 0.f, 0.f, 0.f);

    for (int t = 0; t < T; ++t) {
        const int sl = t & 1;
        mbar_wait(fullb[sl], (t >> 1) & 1);

        const unsigned char* buf = smem + sl * TILE_B + lane * 16;
        int rows = nblk - t * TROWS; if (rows > TROWS) rows = TROWS;
        const int r = warp * 4;

        if (r + 4 <= rows) {
            const unsigned char* p = buf + r * ROWB;
            float4 h0 = *reinterpret_cast<const float4*>(p);
            float4 h1 = *reinterpret_cast<const float4*>(p + ROWB);
            float4 h2 = *reinterpret_cast<const float4*>(p + 2 * ROWB);
            float4 h3 = *reinterpret_cast<const float4*>(p + 3 * ROWB);

            float d0 = dot4(h0, aj);
            float d1 = dot4(h1, aj);
            float d2 = dot4(h2, aj);
            float d3 = dot4(h3, aj);
            #pragma unroll
            for (int o = 16; o > 0; o >>= 1) {
                d0 += __shfl_xor_sync(0xffffffffu, d0, o);
                d1 += __shfl_xor_sync(0xffffffffu, d1, o);
                d2 += __shfl_xor_sync(0xffffffffu, d2, o);
                d3 += __shfl_xor_sync(0xffffffffu, d3, o);
            }
            float gm = fmaxf(fmaxf(d0, d1), fmaxf(d2, d3));
            if (gm > m) {
                float c = __expf(m - gm);
                s *= c;
                acc.x *= c; acc.y *= c; acc.z *= c; acc.w *= c;
                m = gm;
            }
            float w0 = __expf(d0 - m);
            float w1 = __expf(d1 - m);
            float w2 = __expf(d2 - m);
            float w3 = __expf(d3 - m);
            s += (w0 + w1) + (w2 + w3);
            acc.x += w0 * h0.x + w1 * h1.x + w2 * h2.x + w3 * h3.x;
            acc.y += w0 * h0.y + w1 * h1.y + w2 * h2.y + w3 * h3.y;
            acc.z += w0 * h0.z + w1 * h1.z + w2 * h2.z + w3 * h3.z;
            acc.w += w0 * h0.w + w1 * h1.w + w2 * h2.w + w3 * h3.w;
        } else {
            for (int j = 0; j < 4; ++j) {
                if (r + j < rows) {
                    float4 h = *reinterpret_cast<const float4*>(buf + (r + j) * ROWB);
                    float d = dot4(h, aj);
                    #pragma unroll
                    for (int o = 16; o > 0; o >>= 1)
                        d += __shfl_xor_sync(0xffffffffu, d, o);
                    upd(d, h, m, s, acc);
                }
            }
        }

        // release this slot
        asm volatile("mbarrier.arrive.shared.b64 _, [%0];" :: "r"(emptyb[sl]) : "memory");

        // refill with tile t+2 once all NT consumers released it
        if (tid == 0 && t + 2 < T) {
            mbar_wait(emptyb[sl], (t >> 1) & 1);
            int rows2 = nblk - (t + 2) * TROWS; if (rows2 > TROWS) rows2 = TROWS;
            uint32_t bytes = (uint32_t)rows2 * ROWB;
            uint32_t dst = sbase + sl * TILE_B;
            asm volatile("mbarrier.arrive.expect_tx.shared.b64 _, [%0], %1;"
                         :: "r"(fullb[sl]), "r"(bytes) : "memory");
            asm volatile("cp.async.bulk.shared::cluster.global.mbarrier::complete_tx::bytes "
                         "[%0], [%1], %2, [%3];"
                         :: "r"(dst), "l"(src0 + (size_t)(t + 2) * TROWS * D),
                            "r"(bytes), "r"(fullb[sl]) : "memory");
        }
    }

    // ---- Block combine (scratch aliases the dead ring) ----
    __syncthreads();
    float* sm_acc  = reinterpret_cast<float*>(smem);            // [WPB][D] 8KB
    float* sm_m    = reinterpret_cast<float*>(smem + 8192);     // [WPB]
    float* sm_s    = reinterpret_cast<float*>(smem + 8256);     // [WPB]
    float* red     = reinterpret_cast<float*>(smem + 8320);     // [WPB]
    float* sm_MS   = reinterpret_cast<float*>(smem + 8384);     // M, S
    float* sm_c    = reinterpret_cast<float*>(smem + 8448);     // [NB]
    float* sm_part = reinterpret_cast<float*>(smem + 8448 + 1280); // [GRP][D]

    if (lane == 0) { sm_m[warp] = m; sm_s[warp] = s; }
    *reinterpret_cast<float4*>(&sm_acc[warp * D + lane * 4]) = acc;
    __syncthreads();

    if (tid < D) {
        const int d = tid;
        float M = -1e30f;
        #pragma unroll
        for (int w = 0; w < WPB; ++w) M = fmaxf(M, sm_m[w]);

        float st = 0.f, ad = 0.f;
        #pragma unroll
        for (int w = 0; w < WPB; ++w) {
            float c = __expf(sm_m[w] - M);
            st += sm_s[w] * c;
            ad += sm_acc[w * D + d] * c;
        }
        g_acc[blockIdx.x * D + d] = ad;
        if (d == 0) { g_m[blockIdx.x] = M; g_s[blockIdx.x] = st; }
    }

    // ---- Last-block-done finalize (partials L2-hot) ----
    __threadfence();
    __shared__ bool isLast;
    if (tid == 0) {
        unsigned v = atomicAdd(&g_count, 1u);
        isLast = (v == NB - 1);
    }
    __syncthreads();
    if (!isLast) return;
    if (tid == 0) g_count = 0;             // reset for graph replay

    float mreg = (tid < NB) ? __ldcg(&g_m[tid]) : -1e30f;
    float mv = mreg;
    #pragma unroll
    for (int o = 16; o > 0; o >>= 1) mv = fmaxf(mv, __shfl_xor_sync(0xffffffffu, mv, o));
    if (lane == 0) red[warp] = mv;
    __syncthreads();
    if (tid == 0) {
        float v = red[0];
        #pragma unroll
        for (int w = 1; w < WPB; ++w) v = fmaxf(v, red[w]);
        sm_MS[0] = v;
    }
    __syncthreads();
    const float M = sm_MS[0];

    float sv = 0.f;
    if (tid < NB) {
        float c = __expf(mreg - M);
        sm_c[tid] = c;
        sv = __ldcg(&g_s[tid]) * c;
    }
    #pragma unroll
    for (int o = 16; o > 0; o >>= 1) sv += __shfl_xor_sync(0xffffffffu, sv, o);
    __syncthreads();
    if (lane == 0) red[warp] = sv;
    __syncthreads();
    if (tid == 0) {
        float v = 0.f;
        #pragma unroll
        for (int w = 0; w < WPB; ++w) v += red[w];
        sm_MS[1] = v;
    }
    __syncthreads();

    const int d   = tid & (D - 1);
    const int grp = tid >> 7;
    float ad = 0.f;
    for (int b = grp; b < NB; b += GRP)
        ad += __ldcg(&g_acc[b * D + d]) * sm_c[b];
    sm_part[grp * D + d] = ad;
    __syncthreads();

    if (tid < D) {
        float total = 0.f;
        #pragma unroll
        for (int g = 0; g < GRP; ++g) total += sm_part[g * D + tid];
        float h = total / sm_MS[1];
        out[tid] = (h > 0.f) ? h : expm1f(h);   // ELU, alpha = 1
    }
}

extern "C" void kernel_launch(void* const* d_in, const int* in_sizes, int n_in,
                              void* d_out, int out_size) {
    // inputs: [0] h_i (unused: constant logit shift cancels in softmax),
    //         [1] h_j [200000,128] f32, [2] a [256,1] f32
    const float* hj = (const float*)d_in[1];
    const float* a  = (const float*)d_in[2];
    const int nrows = in_sizes[1] / D;

    cudaFuncSetAttribute(gat_fused, cudaFuncAttributeMaxDynamicSharedMemorySize, SMEM_B);
    gat_fused<<<NB, NT, SMEM_B>>>(hj, a, nrows, (float*)d_out);
}

// round 11
// speedup vs baseline: 2.0982x; 2.0982x over previous
#include <cuda_runtime.h>
#include <cuda_bf16.h>

// GraphAttentionLayer: out = elu(softmax(h_j @ a_j + const) @ h_j)
// SINGLE kernel. Lane-remapped quad layout: warp = 4 row-groups x 8 lanes,
// lane owns a 16-dim slice -> dot reduce needs 3 SHFLs per 4 rows (was 20),
// slashing MIO/LSU port pressure that capped all LDG variants at ~4.4TB/s.
// Per-group online softmax, warp-combined once at the end (xor 8,16).
// Last-block-done finalize combines partials L2-hot.
// h_i . a_i is a constant logit shift -> cancels in softmax -> skipped.

#define D        128
#define NB       296          // 2 blocks/SM on 148 SMs
#define NT       512
#define WPB      (NT / 32)    // 16 warps
#define NW       (NB * WPB)   // 4736 warps
#define GRP      (NT / D)     // 4 finalize groups
#define NEGBIG   (-3.0e38f)   // "minus inf" that still exps to 0 against -1e30

__device__ float g_m[NB];
__device__ float g_s[NB];
__device__ float g_acc[NB * D];
__device__ unsigned int g_count;

__device__ __forceinline__ float dot4(const float4& h, const float4& a) {
    return h.x * a.x + h.y * a.y + h.z * a.z + h.w * a.w;
}

__global__ __launch_bounds__(NT, 2)
void gat_fused(const float* __restrict__ hj, const float* __restrict__ a,
               int nrows, float* __restrict__ out) {
    const int warp = threadIdx.x >> 5;
    const int lane = threadIdx.x & 31;
    const int grp  = lane >> 3;        // 0..3 : row within quad
    const int sub  = lane & 7;         // 0..7 : 16B piece within 128B line

    // lane's 16-dim slice of a_j: dims 32*j + sub*4 .. +3
    float4 aj[4];
    #pragma unroll
    for (int j = 0; j < 4; ++j)
        aj[j] = *reinterpret_cast<const float4*>(a + D + j * 32 + sub * 4);

    const int gw    = blockIdx.x * WPB + warp;
    int chunk = (nrows + NW - 1) / NW;
    chunk = (chunk + 3) & ~3;                       // multiple of 4
    int r0 = gw * chunk;
    int r1 = r0 + chunk;
    if (r0 > nrows) r0 = nrows;
    if (r1 > nrows) r1 = nrows;
    const int n = r1 - r0;

    float  m = -1e30f;
    float  s = 0.0f;
    float4 acc[4];
    #pragma unroll
    for (int j = 0; j < 4; ++j) acc[j] = make_float4(0.f, 0.f, 0.f, 0.f);

    // base points at (row r0+grp, byte sub*16)
    const char* base = reinterpret_cast<const char*>(hj + (size_t)r0 * D)
                     + grp * 512 + sub * 16;

    for (int i = 0; i < n; i += 4) {
        const bool valid = (i + grp) < n;
        // clamp invalid groups to row i (always valid; weight forced to 0)
        const char* p = base + (size_t)i * 512 - (valid ? 0 : grp * 512);

        float4 h0 = __ldcg(reinterpret_cast<const float4*>(p));
        float4 h1 = __ldcg(reinterpret_cast<const float4*>(p + 128));
        float4 h2 = __ldcg(reinterpret_cast<const float4*>(p + 256));
        float4 h3 = __ldcg(reinterpret_cast<const float4*>(p + 384));

        float d = dot4(h0, aj[0]) + dot4(h1, aj[1])
                + dot4(h2, aj[2]) + dot4(h3, aj[3]);
        // reduce across the 8 lanes of this group: 3 SHFLs total
        d += __shfl_xor_sync(0xffffffffu, d, 1);
        d += __shfl_xor_sync(0xffffffffu, d, 2);
        d += __shfl_xor_sync(0xffffffffu, d, 4);
        if (!valid) d = NEGBIG;                    // w -> 0

        if (d > m) {                                // group-uniform, rare
            float c = __expf(m - d);
            s *= c;
            #pragma unroll
            for (int j = 0; j < 4; ++j) {
                acc[j].x *= c; acc[j].y *= c; acc[j].z *= c; acc[j].w *= c;
            }
            m = d;
        }
        float w = __expf(d - m);
        s += w;
        acc[0].x += w * h0.x; acc[0].y += w * h0.y; acc[0].z += w * h0.z; acc[0].w += w * h0.w;
        acc[1].x += w * h1.x; acc[1].y += w * h1.y; acc[1].z += w * h1.z; acc[1].w += w * h1.w;
        acc[2].x += w * h2.x; acc[2].y += w * h2.y; acc[2].z += w * h2.z; acc[2].w += w * h2.w;
        acc[3].x += w * h3.x; acc[3].y += w * h3.y; acc[3].z += w * h3.z; acc[3].w += w * h3.w;
    }

    // ---- Combine the 4 groups within the warp (xor 8, then 16) ----
    #pragma unroll
    for (int o = 8; o <= 16; o <<= 1) {
        float m2 = __shfl_xor_sync(0xffffffffu, m, o);
        float s2 = __shfl_xor_sync(0xffffffffu, s, o);
        float mn = fmaxf(m, m2);
        float c1 = __expf(m - mn);
        float c2 = __expf(m2 - mn);
        s = s * c1 + s2 * c2;
        #pragma unroll
        for (int j = 0; j < 4; ++j) {
            float4 a2;
            a2.x = __shfl_xor_sync(0xffffffffu, acc[j].x, o);
            a2.y = __shfl_xor_sync(0xffffffffu, acc[j].y, o);
            a2.z = __shfl_xor_sync(0xffffffffu, acc[j].z, o);
            a2.w = __shfl_xor_sync(0xffffffffu, acc[j].w, o);
            acc[j].x = acc[j].x * c1 + a2.x * c2;
            acc[j].y = acc[j].y * c1 + a2.y * c2;
            acc[j].z = acc[j].z * c1 + a2.z * c2;
            acc[j].w = acc[j].w * c1 + a2.w * c2;
        }
        m = mn;
    }
    // now every lane holds the warp partial for its sub's 16 dims

    // ---- Block combine in shared memory ----
    __shared__ float sm_m[WPB];
    __shared__ float sm_s[WPB];
    __shared__ __align__(16) float sm_acc[WPB][D];

    if (lane < 8) {
        #pragma unroll
        for (int j = 0; j < 4; ++j)
            *reinterpret_cast<float4*>(&sm_acc[warp][j * 32 + lane * 4]) = acc[j];
    }
    if (lane == 0) { sm_m[warp] = m; sm_s[warp] = s; }
    __syncthreads();

    if (threadIdx.x < D) {
        const int d = threadIdx.x;
        float M = -1e30f;
        #pragma unroll
        for (int w = 0; w < WPB; ++w) M = fmaxf(M, sm_m[w]);

        float st = 0.f, ad = 0.f;
        #pragma unroll
        for (int w = 0; w < WPB; ++w) {
            float c = __expf(sm_m[w] - M);
            st += sm_s[w] * c;
            ad += sm_acc[w][d] * c;
        }
        g_acc[blockIdx.x * D + d] = ad;
        if (d == 0) { g_m[blockIdx.x] = M; g_s[blockIdx.x] = st; }
    }

    // ---- Last-block-done finalize (partials L2-hot) ----
    __threadfence();
    __shared__ bool isLast;
    if (threadIdx.x == 0) {
        unsigned v = atomicAdd(&g_count, 1u);
        isLast = (v == NB - 1);
    }
    __syncthreads();
    if (!isLast) return;
    if (threadIdx.x == 0) g_count = 0;     // reset for graph replay

    const int t = threadIdx.x;
    __shared__ float red[WPB];
    __shared__ float sm_M, sm_S;
    __shared__ float sm_c[NB];
    __shared__ __align__(16) float sm_part[GRP][D];

    float mreg = (t < NB) ? __ldcg(&g_m[t]) : -1e30f;
    float mv = mreg;
    #pragma unroll
    for (int o = 16; o > 0; o >>= 1) mv = fmaxf(mv, __shfl_xor_sync(0xffffffffu, mv, o));
    if (lane == 0) red[warp] = mv;
    __syncthreads();
    if (t == 0) {
        float v = red[0];
        #pragma unroll
        for (int w = 1; w < WPB; ++w) v = fmaxf(v, red[w]);
        sm_M = v;
    }
    __syncthreads();
    const float M = sm_M;

    float sv = 0.f;
    if (t < NB) {
        float c = __expf(mreg - M);
        sm_c[t] = c;
        sv = __ldcg(&g_s[t]) * c;
    }
    #pragma unroll
    for (int o = 16; o > 0; o >>= 1) sv += __shfl_xor_sync(0xffffffffu, sv, o);
    __syncthreads();
    if (lane == 0) red[warp] = sv;
    __syncthreads();
    if (t == 0) {
        float v = 0.f;
        #pragma unroll
        for (int w = 0; w < WPB; ++w) v += red[w];
        sm_S = v;
    }
    __syncthreads();

    const int d    = t & (D - 1);
    const int fg   = t >> 7;
    float ad = 0.f;
    for (int b = fg; b < NB; b += GRP)
        ad += __ldcg(&g_acc[b * D + d]) * sm_c[b];
    sm_part[fg][d] = ad;
    __syncthreads();

    if (t < D) {
        float total = 0.f;
        #pragma unroll
        for (int g = 0; g < GRP; ++g) total += sm_part[g][t];
        float h = total / sm_S;
        out[t] = (h > 0.f) ? h : expm1f(h);    // ELU, alpha = 1
    }
}

extern "C" void kernel_launch(void* const* d_in, const int* in_sizes, int n_in,
                              void* d_out, int out_size) {
    // inputs: [0] h_i (unused: constant logit shift cancels in softmax),
    //         [1] h_j [200000,128] f32, [2] a [256,1] f32
    const float* hj = (const float*)d_in[1];
    const float* a  = (const float*)d_in[2];
    const int nrows = in_sizes[1] / D;

    gat_fused<<<NB, NT>>>(hj, a, nrows, (float*)d_out);
}